// round 1
// baseline (speedup 1.0000x reference)
#include <cuda_runtime.h>
#include <math.h>

// ---------------------------------------------------------------------------
// Scratch (no allocations allowed): latent (B,224) and h (B,392)
// ---------------------------------------------------------------------------
#define BATCH 16384
__device__ float g_latent[BATCH * 224];
__device__ float g_h[BATCH * 392];

// ---------------------------------------------------------------------------
// packed f32x2 helpers (sm_100+)
// ---------------------------------------------------------------------------
__device__ __forceinline__ unsigned long long pack2(float x, float y) {
    unsigned long long r;
    asm("mov.b64 %0, {%1, %2};" : "=l"(r) : "f"(x), "f"(y));
    return r;
}
__device__ __forceinline__ void unpack2(unsigned long long v, float& x, float& y) {
    asm("mov.b64 {%0, %1}, %2;" : "=f"(x), "=f"(y) : "l"(v));
}
__device__ __forceinline__ void fma2(unsigned long long& d, unsigned long long a, unsigned long long b) {
    asm("fma.rn.f32x2 %0, %1, %2, %0;" : "+l"(d) : "l"(a), "l"(b));
}

// ---------------------------------------------------------------------------
// Kernel 1: quadrant means -> 4-qubit sim -> latent = relu(qf @ w_lat^T + b)
// One warp per sample. 256 threads/block = 8 samples/block.
// ---------------------------------------------------------------------------
__global__ void __launch_bounds__(256) k1_quad_latent(
    const float* __restrict__ x,
    const float* __restrict__ var_params,
    const float* __restrict__ w_lat,
    const float* __restrict__ b_lat)
{
    const int warp = threadIdx.x >> 5;
    const int lane = threadIdx.x & 31;
    const int b = blockIdx.x * 8 + warp;

    const float* xb = x + (size_t)b * 784;
    float q0 = 0.f, q1 = 0.f, q2 = 0.f, q3 = 0.f;
    for (int idx = lane; idx < 784; idx += 32) {
        float v = xb[idx];
        int i = idx / 28, j = idx - i * 28;
        if (i < 14) { if (j < 14) q0 += v; else q1 += v; }
        else        { if (j < 14) q2 += v; else q3 += v; }
    }
#pragma unroll
    for (int off = 16; off; off >>= 1) {
        q0 += __shfl_xor_sync(0xFFFFFFFFu, q0, off);
        q1 += __shfl_xor_sync(0xFFFFFFFFu, q1, off);
        q2 += __shfl_xor_sync(0xFFFFFFFFu, q2, off);
        q3 += __shfl_xor_sync(0xFFFFFFFFu, q3, off);
    }
    const float inv196 = 1.0f / 196.0f;
    float ang[4] = { q0 * inv196, q1 * inv196, q2 * inv196, q3 * inv196 };

    // RY(ang[q]) from |0>: amplitude product state (real)
    float cc[4], ss[4];
#pragma unroll
    for (int q = 0; q < 4; q++) {
        float th = 0.5f * ang[q];
        cc[q] = cosf(th);
        ss[q] = sinf(th);
    }
    float re[16], im[16];
#pragma unroll
    for (int i = 0; i < 16; i++) {
        re[i] = ((i & 8) ? ss[0] : cc[0]) * ((i & 4) ? ss[1] : cc[1]) *
                ((i & 2) ? ss[2] : cc[2]) * ((i & 1) ? ss[3] : cc[3]);
        im[i] = 0.f;
    }
    // for q in 0..3: RZ(params[q]) on q, then CNOT(q, (q+1)%4)
#pragma unroll
    for (int q = 0; q < 4; q++) {
        float ph = 0.5f * var_params[q];
        float hc = cosf(ph), hs = sinf(ph);
        const int mq = 8 >> q;
        const int mt = 8 >> ((q + 1) & 3);
#pragma unroll
        for (int i = 0; i < 16; i++) {
            float sg = (i & mq) ? hs : -hs;   // e^{+i ph} if bit=1 else e^{-i ph}
            float nr = re[i] * hc - im[i] * sg;
            float ni = re[i] * sg + im[i] * hc;
            re[i] = nr; im[i] = ni;
        }
#pragma unroll
        for (int i = 0; i < 16; i++) {
            if ((i & mq) && !(i & mt)) {
                int j2 = i | mt;
                float tr = re[i]; re[i] = re[j2]; re[j2] = tr;
                float ti = im[i]; im[i] = im[j2]; im[j2] = ti;
            }
        }
    }
    float z0 = 0.f, z1 = 0.f, z2 = 0.f, z3 = 0.f;
#pragma unroll
    for (int i = 0; i < 16; i++) {
        float p = re[i] * re[i] + im[i] * im[i];
        z0 += (i & 8) ? -p : p;
        z1 += (i & 4) ? -p : p;
        z2 += (i & 2) ? -p : p;
        z3 += (i & 1) ? -p : p;
    }
    // latent
    for (int r = lane; r < 224; r += 32) {
        float4 w = *(const float4*)(w_lat + (size_t)r * 4);
        float a = b_lat[r];
        a = fmaf(w.x, z0, a);
        a = fmaf(w.y, z1, a);
        a = fmaf(w.z, z2, a);
        a = fmaf(w.w, z3, a);
        g_latent[(size_t)b * 224 + r] = fmaxf(a, 0.f);
    }
}

// ---------------------------------------------------------------------------
// Kernel 2: h = relu(latent @ w_fc^T + b_fc)   [16384x224]@[224x392]
// BM=128, BN=64 (N padded to 448), TM=4, TN=8, packed f32x2 FMA.
// Whole K=224 staged in smem: slat [224][132], sw [224][68] = 179200 B.
// ---------------------------------------------------------------------------
#define GK   224
#define SLM  132
#define SWN  68
__global__ void __launch_bounds__(256, 1) k2_gemm(
    const float* __restrict__ w_fc,
    const float* __restrict__ b_fc)
{
    extern __shared__ float sm[];
    float* slat = sm;              // [GK][SLM]
    float* sw   = sm + GK * SLM;   // [GK][SWN]

    const int tid = threadIdx.x;
    const int n0 = blockIdx.x * 64;
    const int m0 = blockIdx.y * 128;

    // stage latent transposed: [k][m]
    for (int idx = tid; idx < 128 * 56; idx += 256) {
        int m = idx / 56;
        int k4 = (idx - m * 56) * 4;
        float4 v = *(const float4*)(g_latent + (size_t)(m0 + m) * GK + k4);
        slat[(k4 + 0) * SLM + m] = v.x;
        slat[(k4 + 1) * SLM + m] = v.y;
        slat[(k4 + 2) * SLM + m] = v.z;
        slat[(k4 + 3) * SLM + m] = v.w;
    }
    // stage weights transposed: [k][n]  (zero-pad n >= 392)
    for (int idx = tid; idx < 64 * 56; idx += 256) {
        int n = idx / 56;
        int k4 = (idx - n * 56) * 4;
        int gn = n0 + n;
        float4 v = make_float4(0.f, 0.f, 0.f, 0.f);
        if (gn < 392) v = *(const float4*)(w_fc + (size_t)gn * GK + k4);
        sw[(k4 + 0) * SWN + n] = v.x;
        sw[(k4 + 1) * SWN + n] = v.y;
        sw[(k4 + 2) * SWN + n] = v.z;
        sw[(k4 + 3) * SWN + n] = v.w;
    }
    __syncthreads();

    const int tm = tid & 31;   // sample group (lane)
    const int tn = tid >> 5;   // output group (warp)
    const float* lp = slat + tm * 4;
    const float* wp = sw + tn * 8;

    unsigned long long acc[2][8];
#pragma unroll
    for (int p = 0; p < 2; p++)
#pragma unroll
        for (int j = 0; j < 8; j++) acc[p][j] = 0ull;

#pragma unroll 4
    for (int k = 0; k < GK; k++) {
        float4 la = *(const float4*)(lp + k * SLM);
        float4 wa = *(const float4*)(wp + k * SWN);
        float4 wb = *(const float4*)(wp + k * SWN + 4);
        unsigned long long l0 = pack2(la.x, la.y);
        unsigned long long l1 = pack2(la.z, la.w);
        unsigned long long w2[8];
        w2[0] = pack2(wa.x, wa.x); w2[1] = pack2(wa.y, wa.y);
        w2[2] = pack2(wa.z, wa.z); w2[3] = pack2(wa.w, wa.w);
        w2[4] = pack2(wb.x, wb.x); w2[5] = pack2(wb.y, wb.y);
        w2[6] = pack2(wb.z, wb.z); w2[7] = pack2(wb.w, wb.w);
#pragma unroll
        for (int j = 0; j < 8; j++) {
            fma2(acc[0][j], l0, w2[j]);
            fma2(acc[1][j], l1, w2[j]);
        }
    }
    __syncthreads();

    // epilogue: bias + relu, stage through smem for coalesced global writes
    float bias[8];
#pragma unroll
    for (int j = 0; j < 8; j++) {
        int gn = n0 + tn * 8 + j;
        bias[j] = (gn < 392) ? b_fc[gn] : 0.f;
    }
    float* sh = sm;  // [128][65]
#pragma unroll
    for (int p = 0; p < 2; p++) {
#pragma unroll
        for (int j = 0; j < 8; j++) {
            float x0, x1;
            unpack2(acc[p][j], x0, x1);
            int ml = tm * 4 + p * 2;
            int nl = tn * 8 + j;
            sh[(ml + 0) * 65 + nl] = fmaxf(x0 + bias[j], 0.f);
            sh[(ml + 1) * 65 + nl] = fmaxf(x1 + bias[j], 0.f);
        }
    }
    __syncthreads();
    for (int idx = tid; idx < 128 * 64; idx += 256) {
        int m = idx >> 6, n = idx & 63;
        int gn = n0 + n;
        if (gn < 392) g_h[(size_t)(m0 + m) * 392 + gn] = sh[m * 65 + n];
    }
}

// ---------------------------------------------------------------------------
// Kernel 3: deconv1(2x2,s2) + relu + deconv2(2x2,s2) + sigmoid
// One block (128 threads) per sample.
// ---------------------------------------------------------------------------
__global__ void __launch_bounds__(128) k3_deconv(
    const float* __restrict__ w_d1, const float* __restrict__ b_d1,
    const float* __restrict__ w_d2, const float* __restrict__ b_d2,
    float* __restrict__ out)
{
    __shared__ float sh[392];
    __shared__ float sy[784];
    __shared__ float swd1[128];
    __shared__ float swd2[16];
    __shared__ float sb1[4];
    __shared__ float sb2;

    const int b = blockIdx.x;
    const int tid = threadIdx.x;

    const float* hb = g_h + (size_t)b * 392;
    for (int idx = tid; idx < 392; idx += 128) sh[idx] = hb[idx];
    swd1[tid] = w_d1[tid];                    // 128 threads, 128 weights
    if (tid < 16) swd2[tid] = w_d2[tid];
    if (tid < 4)  sb1[tid] = b_d1[tid];
    if (tid == 0) sb2 = b_d2[0];
    __syncthreads();

    // deconv1: h(8,7,7) -> y1(4,14,14), w_d1 (Ci=8,Co=4,2,2)
    for (int p = tid; p < 784; p += 128) {
        int o = p / 196;
        int rem = p - o * 196;
        int I = rem / 14, J = rem - (rem / 14) * 14;
        int i = I >> 1, d = I & 1, j = J >> 1, kk = J & 1;
        float acc = sb1[o];
#pragma unroll
        for (int c = 0; c < 8; c++)
            acc = fmaf(sh[c * 49 + i * 7 + j], swd1[c * 16 + o * 4 + d * 2 + kk], acc);
        sy[p] = fmaxf(acc, 0.f);
    }
    __syncthreads();

    // deconv2: y1(4,14,14) -> out(1,28,28), w_d2 (Ci=4,Co=1,2,2), sigmoid
    float* ob = out + (size_t)b * 784;
    for (int p = tid; p < 784; p += 128) {
        int r = p / 28, c = p - (p / 28) * 28;
        int I = r >> 1, d = r & 1, J = c >> 1, kk = c & 1;
        float acc = sb2;
#pragma unroll
        for (int o = 0; o < 4; o++)
            acc = fmaf(sy[o * 196 + I * 14 + J], swd2[o * 4 + d * 2 + kk], acc);
        ob[p] = 1.0f / (1.0f + __expf(-acc));
    }
}

// ---------------------------------------------------------------------------
// Launch
// ---------------------------------------------------------------------------
extern "C" void kernel_launch(void* const* d_in, const int* in_sizes, int n_in,
                              void* d_out, int out_size)
{
    const float* x          = (const float*)d_in[0];
    const float* var_params = (const float*)d_in[1];
    const float* w_lat      = (const float*)d_in[2];
    const float* b_lat      = (const float*)d_in[3];
    const float* w_fc       = (const float*)d_in[4];
    const float* b_fc       = (const float*)d_in[5];
    const float* w_d1       = (const float*)d_in[6];
    const float* b_d1       = (const float*)d_in[7];
    const float* w_d2       = (const float*)d_in[8];
    const float* b_d2       = (const float*)d_in[9];
    float* out = (float*)d_out;

    static bool attr_set = false;
    if (!attr_set) {
        cudaFuncSetAttribute(k2_gemm, cudaFuncAttributeMaxDynamicSharedMemorySize,
                             (GK * SLM + GK * SWN) * (int)sizeof(float));
        attr_set = true;
    }

    k1_quad_latent<<<BATCH / 8, 256>>>(x, var_params, w_lat, b_lat);
    k2_gemm<<<dim3(7, BATCH / 128), 256, (GK * SLM + GK * SWN) * sizeof(float)>>>(w_fc, b_fc);
    k3_deconv<<<BATCH, 128>>>(w_d1, b_d1, w_d2, b_d2, out);
}

// round 2
// speedup vs baseline: 1.1740x; 1.1740x over previous
#include <cuda_runtime.h>
#include <math.h>

#define BATCH 16384
__device__ float g_latent[BATCH * 224];
__device__ float g_h[BATCH * 392];

// ---------------------------------------------------------------------------
// packed f32x2 helpers (sm_100+)
// ---------------------------------------------------------------------------
__device__ __forceinline__ unsigned long long pack2(float x, float y) {
    unsigned long long r;
    asm("mov.b64 %0, {%1, %2};" : "=l"(r) : "f"(x), "f"(y));
    return r;
}
__device__ __forceinline__ void unpack2(unsigned long long v, float& x, float& y) {
    asm("mov.b64 {%0, %1}, %2;" : "=f"(x), "=f"(y) : "l"(v));
}
__device__ __forceinline__ void fma2(unsigned long long& d, unsigned long long a, unsigned long long b) {
    asm("fma.rn.f32x2 %0, %1, %2, %0;" : "+l"(d) : "l"(a), "l"(b));
}

// ---------------------------------------------------------------------------
// Kernel 1: quadrant means -> 4-qubit sim -> latent = relu(qf @ w_lat^T + b)
// One warp per sample; float4 loads; arithmetic quadrant split.
// ---------------------------------------------------------------------------
__global__ void __launch_bounds__(256) k1_quad_latent(
    const float* __restrict__ x,
    const float* __restrict__ var_params,
    const float* __restrict__ w_lat,
    const float* __restrict__ b_lat)
{
    const int warp = threadIdx.x >> 5;
    const int lane = threadIdx.x & 31;
    const int b = blockIdx.x * 8 + warp;

    const float4* xb4 = (const float4*)(x + (size_t)b * 784);
    float q0 = 0.f, q1 = 0.f, q2 = 0.f, q3 = 0.f;
#pragma unroll
    for (int it = 0; it < 7; it++) {
        int f = lane + 32 * it;          // float4 index, 196 per sample
        if (f < 196) {
            float4 v = xb4[f];
            int row = f / 7;
            int cg  = f - row * 7;
            float s4  = (v.x + v.y) + (v.z + v.w);
            float lft = (cg < 3) ? s4 : ((cg == 3) ? (v.x + v.y) : 0.f);
            float rgt = s4 - lft;
            if (row < 14) { q0 += lft; q1 += rgt; }
            else          { q2 += lft; q3 += rgt; }
        }
    }
#pragma unroll
    for (int off = 16; off; off >>= 1) {
        q0 += __shfl_xor_sync(0xFFFFFFFFu, q0, off);
        q1 += __shfl_xor_sync(0xFFFFFFFFu, q1, off);
        q2 += __shfl_xor_sync(0xFFFFFFFFu, q2, off);
        q3 += __shfl_xor_sync(0xFFFFFFFFu, q3, off);
    }
    const float inv196 = 1.0f / 196.0f;
    float ang[4] = { q0 * inv196, q1 * inv196, q2 * inv196, q3 * inv196 };

    float cc[4], ss[4];
#pragma unroll
    for (int q = 0; q < 4; q++) {
        float th = 0.5f * ang[q];
        cc[q] = cosf(th);
        ss[q] = sinf(th);
    }
    float re[16], im[16];
#pragma unroll
    for (int i = 0; i < 16; i++) {
        re[i] = ((i & 8) ? ss[0] : cc[0]) * ((i & 4) ? ss[1] : cc[1]) *
                ((i & 2) ? ss[2] : cc[2]) * ((i & 1) ? ss[3] : cc[3]);
        im[i] = 0.f;
    }
#pragma unroll
    for (int q = 0; q < 4; q++) {
        float ph = 0.5f * var_params[q];
        float hc = cosf(ph), hs = sinf(ph);
        const int mq = 8 >> q;
        const int mt = 8 >> ((q + 1) & 3);
#pragma unroll
        for (int i = 0; i < 16; i++) {
            float sg = (i & mq) ? hs : -hs;
            float nr = re[i] * hc - im[i] * sg;
            float ni = re[i] * sg + im[i] * hc;
            re[i] = nr; im[i] = ni;
        }
#pragma unroll
        for (int i = 0; i < 16; i++) {
            if ((i & mq) && !(i & mt)) {
                int j2 = i | mt;
                float tr = re[i]; re[i] = re[j2]; re[j2] = tr;
                float ti = im[i]; im[i] = im[j2]; im[j2] = ti;
            }
        }
    }
    float z0 = 0.f, z1 = 0.f, z2 = 0.f, z3 = 0.f;
#pragma unroll
    for (int i = 0; i < 16; i++) {
        float p = re[i] * re[i] + im[i] * im[i];
        z0 += (i & 8) ? -p : p;
        z1 += (i & 4) ? -p : p;
        z2 += (i & 2) ? -p : p;
        z3 += (i & 1) ? -p : p;
    }
    for (int r = lane; r < 224; r += 32) {
        float4 w = *(const float4*)(w_lat + (size_t)r * 4);
        float a = b_lat[r];
        a = fmaf(w.x, z0, a);
        a = fmaf(w.y, z1, a);
        a = fmaf(w.z, z2, a);
        a = fmaf(w.w, z3, a);
        g_latent[(size_t)b * 224 + r] = fmaxf(a, 0.f);
    }
}

// ---------------------------------------------------------------------------
// Kernel 2: h = relu(latent @ w_fc^T + b_fc)   [16384x224]@[392x224]^T
// BM=256, BN=64, TM=8 (two groups of 4), TN=8, K in 2 chunks of 112.
// Per k per warp: 2 LDS.128 latent + 2 broadcast LDS.128 weights vs 32 FFMA2
// -> fma-pipe-bound.
// ---------------------------------------------------------------------------
#define GK     224
#define KCH    112
#define SLSTR  260   // slat row stride (floats): mult of 4 for LDS.128, not mult of 32 banks
#define SWSTR  68
#define SLAT_FLOATS (KCH * SLSTR)
#define SW_FLOATS   (KCH * SWSTR)
#define K2_SMEM_BYTES ((SLAT_FLOATS + SW_FLOATS) * 4)

__global__ void __launch_bounds__(256, 1) k2_gemm(
    const float* __restrict__ w_fc,
    const float* __restrict__ b_fc)
{
    extern __shared__ float sm[];
    float* slat = sm;                   // [KCH][SLSTR]
    float* sw   = sm + SLAT_FLOATS;     // [KCH][SWSTR]

    const int tid = threadIdx.x;
    const int n0 = blockIdx.x * 64;
    const int m0 = blockIdx.y * 256;
    const int tm = tid & 31;
    const int tn = tid >> 5;

    unsigned long long acc[4][8];
#pragma unroll
    for (int p = 0; p < 4; p++)
#pragma unroll
        for (int j = 0; j < 8; j++) acc[p][j] = 0ull;

    for (int ch = 0; ch < 2; ch++) {
        const int kb = ch * KCH;
        // ---- stage latent chunk transposed: slat[k][m] ----
        for (int idx = tid; idx < 256 * 28; idx += 256) {
            int m = idx / 28;
            int f = idx - m * 28;                 // float4 index within chunk
            float4 v = *(const float4*)(g_latent + (size_t)(m0 + m) * GK + kb + f * 4);
            int k = f * 4;
            slat[(k + 0) * SLSTR + m] = v.x;
            slat[(k + 1) * SLSTR + m] = v.y;
            slat[(k + 2) * SLSTR + m] = v.z;
            slat[(k + 3) * SLSTR + m] = v.w;
        }
        // ---- stage weight chunk transposed: sw[k][n], zero-pad n >= 392 ----
        for (int idx = tid; idx < 64 * 28; idx += 256) {
            int n = idx / 28;
            int f = idx - n * 28;
            int gn = n0 + n;
            float4 v = make_float4(0.f, 0.f, 0.f, 0.f);
            if (gn < 392) v = *(const float4*)(w_fc + (size_t)gn * GK + kb + f * 4);
            int k = f * 4;
            sw[(k + 0) * SWSTR + n] = v.x;
            sw[(k + 1) * SWSTR + n] = v.y;
            sw[(k + 2) * SWSTR + n] = v.z;
            sw[(k + 3) * SWSTR + n] = v.w;
        }
        __syncthreads();

        const float* lp = slat + tm * 4;
        const float* wp = sw + tn * 8;
#pragma unroll 2
        for (int k = 0; k < KCH; k++) {
            float4 la0 = *(const float4*)(lp + k * SLSTR);
            float4 la1 = *(const float4*)(lp + k * SLSTR + 128);
            float4 wa  = *(const float4*)(wp + k * SWSTR);
            float4 wb  = *(const float4*)(wp + k * SWSTR + 4);
            unsigned long long l0 = pack2(la0.x, la0.y);
            unsigned long long l1 = pack2(la0.z, la0.w);
            unsigned long long l2 = pack2(la1.x, la1.y);
            unsigned long long l3 = pack2(la1.z, la1.w);
            unsigned long long w2[8];
            w2[0] = pack2(wa.x, wa.x); w2[1] = pack2(wa.y, wa.y);
            w2[2] = pack2(wa.z, wa.z); w2[3] = pack2(wa.w, wa.w);
            w2[4] = pack2(wb.x, wb.x); w2[5] = pack2(wb.y, wb.y);
            w2[6] = pack2(wb.z, wb.z); w2[7] = pack2(wb.w, wb.w);
#pragma unroll
            for (int j = 0; j < 8; j++) {
                fma2(acc[0][j], l0, w2[j]);
                fma2(acc[1][j], l1, w2[j]);
                fma2(acc[2][j], l2, w2[j]);
                fma2(acc[3][j], l3, w2[j]);
            }
        }
        __syncthreads();
    }

    // ---- epilogue: bias + relu, stage via smem for coalesced stores ----
    float bias[8];
#pragma unroll
    for (int j = 0; j < 8; j++) {
        int gn = n0 + tn * 8 + j;
        bias[j] = (gn < 392) ? b_fc[gn] : 0.f;
    }
    float* sh = sm;   // [256][68]
#pragma unroll
    for (int p = 0; p < 4; p++) {
        int mb = (p >> 1) * 128 + tm * 4 + (p & 1) * 2;   // pair base m (local)
#pragma unroll
        for (int j = 0; j < 8; j++) {
            float x0, x1;
            unpack2(acc[p][j], x0, x1);
            int nl = tn * 8 + j;
            sh[(mb + 0) * SWSTR + nl] = fmaxf(x0 + bias[j], 0.f);
            sh[(mb + 1) * SWSTR + nl] = fmaxf(x1 + bias[j], 0.f);
        }
    }
    __syncthreads();
    for (int idx = tid; idx < 256 * 16; idx += 256) {
        int m = idx >> 4;
        int n4 = (idx & 15) * 4;
        int gn = n0 + n4;
        if (gn < 392) {
            float4 v = *(const float4*)(sh + m * SWSTR + n4);
            *(float4*)(g_h + (size_t)(m0 + m) * 392 + gn) = v;
        }
    }
}

// ---------------------------------------------------------------------------
// Kernel 3: deconv1(2x2,s2)+relu -> deconv2(2x2,s2)+sigmoid, fully fused.
// 256 threads = 4 samples x 64; thread t<49 = (i,j) of 7x7 computes its
// entire 4x4 output patch in registers (no intermediate smem).
// ---------------------------------------------------------------------------
__global__ void __launch_bounds__(256) k3_deconv(
    const float* __restrict__ w_d1, const float* __restrict__ b_d1,
    const float* __restrict__ w_d2, const float* __restrict__ b_d2,
    float* __restrict__ out)
{
    __shared__ float sh[4 * 392];
    __shared__ float sw1[128];
    __shared__ float sw2[16];
    __shared__ float sb1[4];
    __shared__ float sb2s;

    const int b0 = blockIdx.x * 4;
    const int tid = threadIdx.x;

    if (tid < 128) sw1[tid] = w_d1[tid];
    if (tid >= 128 && tid < 144) sw2[tid - 128] = w_d2[tid - 128];
    if (tid >= 144 && tid < 148) sb1[tid - 144] = b_d1[tid - 144];
    if (tid == 148) sb2s = b_d2[0];
    for (int idx = tid; idx < 4 * 392; idx += 256)
        sh[idx] = g_h[(size_t)b0 * 392 + idx];
    __syncthreads();

    const int s = tid >> 6;
    const int t = tid & 63;
    if (t < 49) {
        const int i = t / 7;
        const int j = t - i * 7;
        const float* hp = sh + s * 392;
        float hc[8];
#pragma unroll
        for (int c = 0; c < 8; c++) hc[c] = hp[c * 49 + i * 7 + j];

        // deconv1: 16 y1 values = y[o][d1*2+k1]
        float y[4][4];
#pragma unroll
        for (int o = 0; o < 4; o++) {
#pragma unroll
            for (int dk = 0; dk < 4; dk++) {
                float a = sb1[o];
#pragma unroll
                for (int c = 0; c < 8; c++)
                    a = fmaf(hc[c], sw1[c * 16 + o * 4 + dk], a);
                y[o][dk] = fmaxf(a, 0.f);
            }
        }
        // deconv2 + sigmoid: 4x4 patch at rows 4i.., cols 4j..
        float patch[4][4];
#pragma unroll
        for (int d1 = 0; d1 < 2; d1++) {
#pragma unroll
            for (int k1 = 0; k1 < 2; k1++) {
#pragma unroll
                for (int d2 = 0; d2 < 2; d2++) {
#pragma unroll
                    for (int k2 = 0; k2 < 2; k2++) {
                        float a = sb2s;
#pragma unroll
                        for (int o = 0; o < 4; o++)
                            a = fmaf(y[o][d1 * 2 + k1], sw2[o * 4 + d2 * 2 + k2], a);
                        patch[2 * d1 + d2][2 * k1 + k2] = 1.0f / (1.0f + __expf(-a));
                    }
                }
            }
        }
        float* ob = out + (size_t)(b0 + s) * 784;
#pragma unroll
        for (int rr = 0; rr < 4; rr++) {
            float4 v = make_float4(patch[rr][0], patch[rr][1], patch[rr][2], patch[rr][3]);
            *(float4*)(ob + (4 * i + rr) * 28 + 4 * j) = v;
        }
    }
}

// ---------------------------------------------------------------------------
// Launch
// ---------------------------------------------------------------------------
extern "C" void kernel_launch(void* const* d_in, const int* in_sizes, int n_in,
                              void* d_out, int out_size)
{
    const float* x          = (const float*)d_in[0];
    const float* var_params = (const float*)d_in[1];
    const float* w_lat      = (const float*)d_in[2];
    const float* b_lat      = (const float*)d_in[3];
    const float* w_fc       = (const float*)d_in[4];
    const float* b_fc       = (const float*)d_in[5];
    const float* w_d1       = (const float*)d_in[6];
    const float* b_d1       = (const float*)d_in[7];
    const float* w_d2       = (const float*)d_in[8];
    const float* b_d2       = (const float*)d_in[9];
    float* out = (float*)d_out;

    static bool attr_set = false;
    if (!attr_set) {
        cudaFuncSetAttribute(k2_gemm, cudaFuncAttributeMaxDynamicSharedMemorySize,
                             K2_SMEM_BYTES);
        attr_set = true;
    }

    k1_quad_latent<<<BATCH / 8, 256>>>(x, var_params, w_lat, b_lat);
    k2_gemm<<<dim3(7, BATCH / 256), 256, K2_SMEM_BYTES>>>(w_fc, b_fc);
    k3_deconv<<<BATCH / 4, 256>>>(w_d1, b_d1, w_d2, b_d2, out);
}

// round 5
// speedup vs baseline: 2.4393x; 2.0778x over previous
#include <cuda_runtime.h>
#include <cuda_bf16.h>
#include <math.h>
#include <cstdint>

#define BATCH 16384
__device__ __nv_bfloat16 g_latent_bf[BATCH * 224];
__device__ __nv_bfloat16 g_wfc_bf[392 * 224];
__device__ float g_h[BATCH * 392];

__device__ __forceinline__ uint32_t smem_u32(const void* p) {
    uint32_t a;
    asm("{ .reg .u64 t; cvta.to.shared.u64 t, %1; cvt.u32.u64 %0, t; }" : "=r"(a) : "l"(p));
    return a;
}
__device__ __forceinline__ void ldmatrix_x4(uint32_t& r0, uint32_t& r1, uint32_t& r2, uint32_t& r3,
                                            uint32_t addr) {
    asm volatile("ldmatrix.sync.aligned.m8n8.x4.shared.b16 {%0,%1,%2,%3}, [%4];"
                 : "=r"(r0), "=r"(r1), "=r"(r2), "=r"(r3) : "r"(addr));
}
__device__ __forceinline__ void mma_16816(float* d, const uint32_t* a, const uint32_t* b) {
    asm volatile(
        "mma.sync.aligned.m16n8k16.row.col.f32.bf16.bf16.f32 "
        "{%0,%1,%2,%3}, {%4,%5,%6,%7}, {%8,%9}, {%0,%1,%2,%3};"
        : "+f"(d[0]), "+f"(d[1]), "+f"(d[2]), "+f"(d[3])
        : "r"(a[0]), "r"(a[1]), "r"(a[2]), "r"(a[3]), "r"(b[0]), "r"(b[1]));
}

// ---------------------------------------------------------------------------
// Kernel 1: quadrant means -> 4-qubit sim -> latent (bf16) = relu(qf@w_lat^T+b)
// One warp per sample; fast-math trig (args small, MUFU err ~5e-7).
// ---------------------------------------------------------------------------
__global__ void __launch_bounds__(256) k1_quad_latent(
    const float* __restrict__ x,
    const float* __restrict__ var_params,
    const float* __restrict__ w_lat,
    const float* __restrict__ b_lat)
{
    const int warp = threadIdx.x >> 5;
    const int lane = threadIdx.x & 31;
    const int b = blockIdx.x * 8 + warp;

    const float4* xb4 = (const float4*)(x + (size_t)b * 784);
    float q0 = 0.f, q1 = 0.f, q2 = 0.f, q3 = 0.f;
#pragma unroll
    for (int it = 0; it < 7; it++) {
        int f = lane + 32 * it;
        if (f < 196) {
            float4 v = xb4[f];
            int row = f / 7;
            int cg  = f - row * 7;
            float s4  = (v.x + v.y) + (v.z + v.w);
            float lft = (cg < 3) ? s4 : ((cg == 3) ? (v.x + v.y) : 0.f);
            float rgt = s4 - lft;
            if (row < 14) { q0 += lft; q1 += rgt; }
            else          { q2 += lft; q3 += rgt; }
        }
    }
#pragma unroll
    for (int off = 16; off; off >>= 1) {
        q0 += __shfl_xor_sync(0xFFFFFFFFu, q0, off);
        q1 += __shfl_xor_sync(0xFFFFFFFFu, q1, off);
        q2 += __shfl_xor_sync(0xFFFFFFFFu, q2, off);
        q3 += __shfl_xor_sync(0xFFFFFFFFu, q3, off);
    }
    const float inv196 = 1.0f / 196.0f;
    float ang[4] = { q0 * inv196, q1 * inv196, q2 * inv196, q3 * inv196 };

    float cc[4], ss[4];
#pragma unroll
    for (int q = 0; q < 4; q++) {
        float th = 0.5f * ang[q];
        cc[q] = __cosf(th);
        ss[q] = __sinf(th);
    }
    float re[16], im[16];
#pragma unroll
    for (int i = 0; i < 16; i++) {
        re[i] = ((i & 8) ? ss[0] : cc[0]) * ((i & 4) ? ss[1] : cc[1]) *
                ((i & 2) ? ss[2] : cc[2]) * ((i & 1) ? ss[3] : cc[3]);
        im[i] = 0.f;
    }
#pragma unroll
    for (int q = 0; q < 4; q++) {
        float ph = 0.5f * var_params[q];
        float hc = __cosf(ph), hs = __sinf(ph);
        const int mq = 8 >> q;
        const int mt = 8 >> ((q + 1) & 3);
#pragma unroll
        for (int i = 0; i < 16; i++) {
            float sg = (i & mq) ? hs : -hs;
            float nr = re[i] * hc - im[i] * sg;
            float ni = re[i] * sg + im[i] * hc;
            re[i] = nr; im[i] = ni;
        }
#pragma unroll
        for (int i = 0; i < 16; i++) {
            if ((i & mq) && !(i & mt)) {
                int j2 = i | mt;
                float tr = re[i]; re[i] = re[j2]; re[j2] = tr;
                float ti = im[i]; im[i] = im[j2]; im[j2] = ti;
            }
        }
    }
    float z0 = 0.f, z1 = 0.f, z2 = 0.f, z3 = 0.f;
#pragma unroll
    for (int i = 0; i < 16; i++) {
        float p = re[i] * re[i] + im[i] * im[i];
        z0 += (i & 8) ? -p : p;
        z1 += (i & 4) ? -p : p;
        z2 += (i & 2) ? -p : p;
        z3 += (i & 1) ? -p : p;
    }
    for (int r = lane; r < 224; r += 32) {
        float4 w = *(const float4*)(w_lat + (size_t)r * 4);
        float a = b_lat[r];
        a = fmaf(w.x, z0, a);
        a = fmaf(w.y, z1, a);
        a = fmaf(w.z, z2, a);
        a = fmaf(w.w, z3, a);
        g_latent_bf[(size_t)b * 224 + r] = __float2bfloat16(fmaxf(a, 0.f));
    }
}

// ---------------------------------------------------------------------------
// Kernel 2a: convert w_fc (392x224 fp32) -> bf16
// ---------------------------------------------------------------------------
__global__ void __launch_bounds__(256) k2a_convert(const float* __restrict__ w_fc) {
    int i = blockIdx.x * 256 + threadIdx.x;
    if (i < 392 * 224 / 4) {
        float4 v = *(const float4*)(w_fc + i * 4);
        __nv_bfloat16* d = g_wfc_bf + i * 4;
        d[0] = __float2bfloat16(v.x);
        d[1] = __float2bfloat16(v.y);
        d[2] = __float2bfloat16(v.z);
        d[3] = __float2bfloat16(v.w);
    }
}

// ---------------------------------------------------------------------------
// Kernel 2: HMMA bf16 GEMM: h = relu(latent @ w_fc^T + b_fc)
// BM=128, BN=64 (N 392 padded to 448), 8 warps (4m x 2n), warp tile 32x32,
// K=224 fully staged. smem row stride 232 bf16 (29 x 16B units, odd -> all
// 8 ldmatrix phases hit distinct banks).
// ---------------------------------------------------------------------------
#define ASTR 232
#define K2_SMEM_BYTES ((128 * ASTR + 64 * ASTR) * 2)

__global__ void __launch_bounds__(256, 2) k2_gemm_mma(
    const float* __restrict__ b_fc)
{
    extern __shared__ __align__(16) __nv_bfloat16 sm[];
    __nv_bfloat16* sa = sm;               // [128][ASTR]
    __nv_bfloat16* sb = sm + 128 * ASTR;  // [64][ASTR]

    const int tid = threadIdx.x;
    const int wid = tid >> 5;
    const int lane = tid & 31;
    const int n0 = blockIdx.x * 64;
    const int m0 = blockIdx.y * 128;
    const int mw = (wid & 3) * 32;   // warp m offset in tile
    const int nw = (wid >> 2) * 32;  // warp n offset in tile

    // ---- stage A: 128 rows x 28 16B-chunks ----
    for (int t = tid; t < 128 * 28; t += 256) {
        int r = t / 28, c = t - (t / 28) * 28;
        uint4 v = *(const uint4*)(g_latent_bf + (size_t)(m0 + r) * 224 + c * 8);
        *(uint4*)(sa + r * ASTR + c * 8) = v;
    }
    // ---- stage B: 64 rows x 28 chunks; zero rows >= 392 ----
    for (int t = tid; t < 64 * 28; t += 256) {
        int r = t / 28, c = t - (t / 28) * 28;
        int gn = n0 + r;
        uint4 v = make_uint4(0u, 0u, 0u, 0u);
        if (gn < 392) v = *(const uint4*)(g_wfc_bf + (size_t)gn * 224 + c * 8);
        *(uint4*)(sb + r * ASTR + c * 8) = v;
    }
    __syncthreads();

    float d[2][4][4];
#pragma unroll
    for (int mt = 0; mt < 2; mt++)
#pragma unroll
        for (int nt = 0; nt < 4; nt++)
#pragma unroll
            for (int e = 0; e < 4; e++) d[mt][nt][e] = 0.f;

    // precomputed smem byte addresses (lane patterns)
    const uint32_t sa_base = smem_u32(sa);
    const uint32_t sb_base = smem_u32(sb);
    // A: row = mw + mt*16 + lane%16 ; col chunk = k0 + (lane>>4)*8
    const int a_row = mw + (lane & 15);
    const int a_coff = (lane >> 4) * 8;
    // B: row = nw + np*16 + (lane&7) + ((lane>>4)&1)*8 ; col = k0 + ((lane>>3)&1)*8
    const int b_row = nw + (lane & 7) + ((lane >> 4) & 1) * 8;
    const int b_coff = ((lane >> 3) & 1) * 8;

#pragma unroll
    for (int ks = 0; ks < 14; ks++) {
        const int k0 = ks * 16;
        uint32_t a0[4], a1[4];
        ldmatrix_x4(a0[0], a0[1], a0[2], a0[3],
                    sa_base + (uint32_t)((a_row) * ASTR + k0 + a_coff) * 2);
        ldmatrix_x4(a1[0], a1[1], a1[2], a1[3],
                    sa_base + (uint32_t)((a_row + 16) * ASTR + k0 + a_coff) * 2);
        uint32_t b01[4], b23[4];
        ldmatrix_x4(b01[0], b01[1], b01[2], b01[3],
                    sb_base + (uint32_t)((b_row) * ASTR + k0 + b_coff) * 2);
        ldmatrix_x4(b23[0], b23[1], b23[2], b23[3],
                    sb_base + (uint32_t)((b_row + 16) * ASTR + k0 + b_coff) * 2);
        // b tiles: {b01[0],b01[1]} = n0..7, {b01[2],b01[3]} = n8..15, etc.
        mma_16816(d[0][0], a0, b01 + 0);
        mma_16816(d[0][1], a0, b01 + 2);
        mma_16816(d[0][2], a0, b23 + 0);
        mma_16816(d[0][3], a0, b23 + 2);
        mma_16816(d[1][0], a1, b01 + 0);
        mma_16816(d[1][1], a1, b01 + 2);
        mma_16816(d[1][2], a1, b23 + 0);
        mma_16816(d[1][3], a1, b23 + 2);
    }

    // ---- epilogue: bias + relu, direct float2 stores ----
    const int qrow = lane >> 2;          // 0..7
    const int qcol = (lane & 3) * 2;     // 0,2,4,6
#pragma unroll
    for (int nt = 0; nt < 4; nt++) {
        int gn = n0 + nw + nt * 8 + qcol;
        if (gn < 392) {
            float2 bv = *(const float2*)(b_fc + gn);
#pragma unroll
            for (int mt = 0; mt < 2; mt++) {
                int m = m0 + mw + mt * 16 + qrow;
                float2 o0, o1;
                o0.x = fmaxf(d[mt][nt][0] + bv.x, 0.f);
                o0.y = fmaxf(d[mt][nt][1] + bv.y, 0.f);
                o1.x = fmaxf(d[mt][nt][2] + bv.x, 0.f);
                o1.y = fmaxf(d[mt][nt][3] + bv.y, 0.f);
                *(float2*)(g_h + (size_t)m * 392 + gn) = o0;
                *(float2*)(g_h + (size_t)(m + 8) * 392 + gn) = o1;
            }
        }
    }
}

// ---------------------------------------------------------------------------
// Kernel 3: deconv1(2x2,s2)+relu -> deconv2(2x2,s2)+sigmoid, fully fused.
// ---------------------------------------------------------------------------
__global__ void __launch_bounds__(256) k3_deconv(
    const float* __restrict__ w_d1, const float* __restrict__ b_d1,
    const float* __restrict__ w_d2, const float* __restrict__ b_d2,
    float* __restrict__ out)
{
    __shared__ float sh[4 * 392];
    __shared__ float sw1[128];
    __shared__ float sw2[16];
    __shared__ float sb1[4];
    __shared__ float sb2s;

    const int b0 = blockIdx.x * 4;
    const int tid = threadIdx.x;

    if (tid < 128) sw1[tid] = w_d1[tid];
    if (tid >= 128 && tid < 144) sw2[tid - 128] = w_d2[tid - 128];
    if (tid >= 144 && tid < 148) sb1[tid - 144] = b_d1[tid - 144];
    if (tid == 148) sb2s = b_d2[0];
    for (int idx = tid; idx < 4 * 392; idx += 256)
        sh[idx] = g_h[(size_t)b0 * 392 + idx];
    __syncthreads();

    const int s = tid >> 6;
    const int t = tid & 63;
    if (t < 49) {
        const int i = t / 7;
        const int j = t - i * 7;
        const float* hp = sh + s * 392;
        float hc[8];
#pragma unroll
        for (int c = 0; c < 8; c++) hc[c] = hp[c * 49 + i * 7 + j];

        float y[4][4];
#pragma unroll
        for (int o = 0; o < 4; o++) {
#pragma unroll
            for (int dk = 0; dk < 4; dk++) {
                float a = sb1[o];
#pragma unroll
                for (int c = 0; c < 8; c++)
                    a = fmaf(hc[c], sw1[c * 16 + o * 4 + dk], a);
                y[o][dk] = fmaxf(a, 0.f);
            }
        }
        float patch[4][4];
#pragma unroll
        for (int d1 = 0; d1 < 2; d1++) {
#pragma unroll
            for (int k1 = 0; k1 < 2; k1++) {
#pragma unroll
                for (int d2 = 0; d2 < 2; d2++) {
#pragma unroll
                    for (int k2 = 0; k2 < 2; k2++) {
                        float a = sb2s;
#pragma unroll
                        for (int o = 0; o < 4; o++)
                            a = fmaf(y[o][d1 * 2 + k1], sw2[o * 4 + d2 * 2 + k2], a);
                        patch[2 * d1 + d2][2 * k1 + k2] = 1.0f / (1.0f + __expf(-a));
                    }
                }
            }
        }
        float* ob = out + (size_t)(b0 + s) * 784;
#pragma unroll
        for (int rr = 0; rr < 4; rr++) {
            float4 v = make_float4(patch[rr][0], patch[rr][1], patch[rr][2], patch[rr][3]);
            *(float4*)(ob + (4 * i + rr) * 28 + 4 * j) = v;
        }
    }
}

// ---------------------------------------------------------------------------
// Launch
// ---------------------------------------------------------------------------
extern "C" void kernel_launch(void* const* d_in, const int* in_sizes, int n_in,
                              void* d_out, int out_size)
{
    const float* x          = (const float*)d_in[0];
    const float* var_params = (const float*)d_in[1];
    const float* w_lat      = (const float*)d_in[2];
    const float* b_lat      = (const float*)d_in[3];
    const float* w_fc       = (const float*)d_in[4];
    const float* b_fc       = (const float*)d_in[5];
    const float* w_d1       = (const float*)d_in[6];
    const float* b_d1       = (const float*)d_in[7];
    const float* w_d2       = (const float*)d_in[8];
    const float* b_d2       = (const float*)d_in[9];
    float* out = (float*)d_out;

    cudaFuncSetAttribute(k2_gemm_mma, cudaFuncAttributeMaxDynamicSharedMemorySize,
                         K2_SMEM_BYTES);

    k1_quad_latent<<<BATCH / 8, 256>>>(x, var_params, w_lat, b_lat);
    k2a_convert<<<(392 * 224 / 4 + 255) / 256, 256>>>(w_fc);
    k2_gemm_mma<<<dim3(7, BATCH / 128), 256, K2_SMEM_BYTES>>>(b_fc);
    k3_deconv<<<BATCH / 4, 256>>>(w_d1, b_d1, w_d2, b_d2, out);
}

// round 6
// speedup vs baseline: 2.6484x; 1.0857x over previous
#include <cuda_runtime.h>
#include <cuda_bf16.h>
#include <math.h>
#include <cstdint>

#define BATCH 16384
__device__ __nv_bfloat16 g_latent_bf[BATCH * 224];
__device__ __nv_bfloat16 g_wfc_bf[392 * 224];
__device__ float g_h[BATCH * 392];

__device__ __forceinline__ uint32_t smem_u32(const void* p) {
    uint32_t a;
    asm("{ .reg .u64 t; cvta.to.shared.u64 t, %1; cvt.u32.u64 %0, t; }" : "=r"(a) : "l"(p));
    return a;
}
__device__ __forceinline__ void ldmatrix_x4(uint32_t& r0, uint32_t& r1, uint32_t& r2, uint32_t& r3,
                                            uint32_t addr) {
    asm volatile("ldmatrix.sync.aligned.m8n8.x4.shared.b16 {%0,%1,%2,%3}, [%4];"
                 : "=r"(r0), "=r"(r1), "=r"(r2), "=r"(r3) : "r"(addr));
}
__device__ __forceinline__ void mma_16816(float* d, const uint32_t* a, const uint32_t* b) {
    asm volatile(
        "mma.sync.aligned.m16n8k16.row.col.f32.bf16.bf16.f32 "
        "{%0,%1,%2,%3}, {%4,%5,%6,%7}, {%8,%9}, {%0,%1,%2,%3};"
        : "+f"(d[0]), "+f"(d[1]), "+f"(d[2]), "+f"(d[3])
        : "r"(a[0]), "r"(a[1]), "r"(a[2]), "r"(a[3]), "r"(b[0]), "r"(b[1]));
}

// ---------------------------------------------------------------------------
// Kernel 1: quadrant means -> 4-qubit sim -> latent (bf16) = relu(qf@w_lat^T+b)
// ---------------------------------------------------------------------------
__global__ void __launch_bounds__(256) k1_quad_latent(
    const float* __restrict__ x,
    const float* __restrict__ var_params,
    const float* __restrict__ w_lat,
    const float* __restrict__ b_lat)
{
    const int warp = threadIdx.x >> 5;
    const int lane = threadIdx.x & 31;
    const int b = blockIdx.x * 8 + warp;

    const float4* xb4 = (const float4*)(x + (size_t)b * 784);
    float q0 = 0.f, q1 = 0.f, q2 = 0.f, q3 = 0.f;
#pragma unroll
    for (int it = 0; it < 7; it++) {
        int f = lane + 32 * it;
        if (f < 196) {
            float4 v = xb4[f];
            int row = f / 7;
            int cg  = f - row * 7;
            float s4  = (v.x + v.y) + (v.z + v.w);
            float lft = (cg < 3) ? s4 : ((cg == 3) ? (v.x + v.y) : 0.f);
            float rgt = s4 - lft;
            if (row < 14) { q0 += lft; q1 += rgt; }
            else          { q2 += lft; q3 += rgt; }
        }
    }
#pragma unroll
    for (int off = 16; off; off >>= 1) {
        q0 += __shfl_xor_sync(0xFFFFFFFFu, q0, off);
        q1 += __shfl_xor_sync(0xFFFFFFFFu, q1, off);
        q2 += __shfl_xor_sync(0xFFFFFFFFu, q2, off);
        q3 += __shfl_xor_sync(0xFFFFFFFFu, q3, off);
    }
    const float inv196 = 1.0f / 196.0f;
    float ang[4] = { q0 * inv196, q1 * inv196, q2 * inv196, q3 * inv196 };

    float cc[4], ss[4];
#pragma unroll
    for (int q = 0; q < 4; q++) {
        float th = 0.5f * ang[q];
        cc[q] = __cosf(th);
        ss[q] = __sinf(th);
    }
    float re[16], im[16];
#pragma unroll
    for (int i = 0; i < 16; i++) {
        re[i] = ((i & 8) ? ss[0] : cc[0]) * ((i & 4) ? ss[1] : cc[1]) *
                ((i & 2) ? ss[2] : cc[2]) * ((i & 1) ? ss[3] : cc[3]);
        im[i] = 0.f;
    }
#pragma unroll
    for (int q = 0; q < 4; q++) {
        float ph = 0.5f * var_params[q];
        float hc = __cosf(ph), hs = __sinf(ph);
        const int mq = 8 >> q;
        const int mt = 8 >> ((q + 1) & 3);
#pragma unroll
        for (int i = 0; i < 16; i++) {
            float sg = (i & mq) ? hs : -hs;
            float nr = re[i] * hc - im[i] * sg;
            float ni = re[i] * sg + im[i] * hc;
            re[i] = nr; im[i] = ni;
        }
#pragma unroll
        for (int i = 0; i < 16; i++) {
            if ((i & mq) && !(i & mt)) {
                int j2 = i | mt;
                float tr = re[i]; re[i] = re[j2]; re[j2] = tr;
                float ti = im[i]; im[i] = im[j2]; im[j2] = ti;
            }
        }
    }
    float z0 = 0.f, z1 = 0.f, z2 = 0.f, z3 = 0.f;
#pragma unroll
    for (int i = 0; i < 16; i++) {
        float p = re[i] * re[i] + im[i] * im[i];
        z0 += (i & 8) ? -p : p;
        z1 += (i & 4) ? -p : p;
        z2 += (i & 2) ? -p : p;
        z3 += (i & 1) ? -p : p;
    }
    for (int r = lane; r < 224; r += 32) {
        float4 w = *(const float4*)(w_lat + (size_t)r * 4);
        float a = b_lat[r];
        a = fmaf(w.x, z0, a);
        a = fmaf(w.y, z1, a);
        a = fmaf(w.z, z2, a);
        a = fmaf(w.w, z3, a);
        g_latent_bf[(size_t)b * 224 + r] = __float2bfloat16(fmaxf(a, 0.f));
    }
}

// ---------------------------------------------------------------------------
// Kernel 2a: convert w_fc (392x224 fp32) -> bf16
// ---------------------------------------------------------------------------
__global__ void __launch_bounds__(256) k2a_convert(const float* __restrict__ w_fc) {
    int i = blockIdx.x * 256 + threadIdx.x;
    if (i < 392 * 224 / 4) {
        float4 v = *(const float4*)(w_fc + i * 4);
        __nv_bfloat16* d = g_wfc_bf + i * 4;
        d[0] = __float2bfloat16(v.x);
        d[1] = __float2bfloat16(v.y);
        d[2] = __float2bfloat16(v.z);
        d[3] = __float2bfloat16(v.w);
    }
}

// ---------------------------------------------------------------------------
// Kernel 2: HMMA bf16 GEMM: h = relu(latent @ w_fc^T + b_fc)
// BM=128, BN=64 (N padded to 448), 8 warps (4m x 2n), warp tile 32x32.
// ---------------------------------------------------------------------------
#define ASTR 232
#define K2_SMEM_BYTES ((128 * ASTR + 64 * ASTR) * 2)

__global__ void __launch_bounds__(256, 2) k2_gemm_mma(
    const float* __restrict__ b_fc)
{
    extern __shared__ __align__(16) __nv_bfloat16 sm[];
    __nv_bfloat16* sa = sm;               // [128][ASTR]
    __nv_bfloat16* sb = sm + 128 * ASTR;  // [64][ASTR]

    const int tid = threadIdx.x;
    const int wid = tid >> 5;
    const int lane = tid & 31;
    const int n0 = blockIdx.x * 64;
    const int m0 = blockIdx.y * 128;
    const int mw = (wid & 3) * 32;
    const int nw = (wid >> 2) * 32;

    for (int t = tid; t < 128 * 28; t += 256) {
        int r = t / 28, c = t - (t / 28) * 28;
        uint4 v = *(const uint4*)(g_latent_bf + (size_t)(m0 + r) * 224 + c * 8);
        *(uint4*)(sa + r * ASTR + c * 8) = v;
    }
    for (int t = tid; t < 64 * 28; t += 256) {
        int r = t / 28, c = t - (t / 28) * 28;
        int gn = n0 + r;
        uint4 v = make_uint4(0u, 0u, 0u, 0u);
        if (gn < 392) v = *(const uint4*)(g_wfc_bf + (size_t)gn * 224 + c * 8);
        *(uint4*)(sb + r * ASTR + c * 8) = v;
    }
    __syncthreads();

    float d[2][4][4];
#pragma unroll
    for (int mt = 0; mt < 2; mt++)
#pragma unroll
        for (int nt = 0; nt < 4; nt++)
#pragma unroll
            for (int e = 0; e < 4; e++) d[mt][nt][e] = 0.f;

    const uint32_t sa_base = smem_u32(sa);
    const uint32_t sb_base = smem_u32(sb);
    const int a_row = mw + (lane & 15);
    const int a_coff = (lane >> 4) * 8;
    const int b_row = nw + (lane & 7) + ((lane >> 4) & 1) * 8;
    const int b_coff = ((lane >> 3) & 1) * 8;

#pragma unroll
    for (int ks = 0; ks < 14; ks++) {
        const int k0 = ks * 16;
        uint32_t a0[4], a1[4];
        ldmatrix_x4(a0[0], a0[1], a0[2], a0[3],
                    sa_base + (uint32_t)((a_row) * ASTR + k0 + a_coff) * 2);
        ldmatrix_x4(a1[0], a1[1], a1[2], a1[3],
                    sa_base + (uint32_t)((a_row + 16) * ASTR + k0 + a_coff) * 2);
        uint32_t b01[4], b23[4];
        ldmatrix_x4(b01[0], b01[1], b01[2], b01[3],
                    sb_base + (uint32_t)((b_row) * ASTR + k0 + b_coff) * 2);
        ldmatrix_x4(b23[0], b23[1], b23[2], b23[3],
                    sb_base + (uint32_t)((b_row + 16) * ASTR + k0 + b_coff) * 2);
        mma_16816(d[0][0], a0, b01 + 0);
        mma_16816(d[0][1], a0, b01 + 2);
        mma_16816(d[0][2], a0, b23 + 0);
        mma_16816(d[0][3], a0, b23 + 2);
        mma_16816(d[1][0], a1, b01 + 0);
        mma_16816(d[1][1], a1, b01 + 2);
        mma_16816(d[1][2], a1, b23 + 0);
        mma_16816(d[1][3], a1, b23 + 2);
    }

    const int qrow = lane >> 2;
    const int qcol = (lane & 3) * 2;
#pragma unroll
    for (int nt = 0; nt < 4; nt++) {
        int gn = n0 + nw + nt * 8 + qcol;
        if (gn < 392) {
            float2 bv = *(const float2*)(b_fc + gn);
#pragma unroll
            for (int mt = 0; mt < 2; mt++) {
                int m = m0 + mw + mt * 16 + qrow;
                float2 o0, o1;
                o0.x = fmaxf(d[mt][nt][0] + bv.x, 0.f);
                o0.y = fmaxf(d[mt][nt][1] + bv.y, 0.f);
                o1.x = fmaxf(d[mt][nt][2] + bv.x, 0.f);
                o1.y = fmaxf(d[mt][nt][3] + bv.y, 0.f);
                *(float2*)(g_h + (size_t)m * 392 + gn) = o0;
                *(float2*)(g_h + (size_t)(m + 8) * 392 + gn) = o1;
            }
        }
    }
}

// ---------------------------------------------------------------------------
// Kernel 3: fused deconv1+relu+deconv2+sigmoid.
// One thread per (sample, I, J) of the 14x14 intermediate grid: computes the
// 4 y1 channels for its (d1,k1) parity, then a 2x2 output patch.
// 16384*196 = 3,211,264 threads; all lanes active; ~30 regs.
// ---------------------------------------------------------------------------
__global__ void __launch_bounds__(256) k3_deconv(
    const float* __restrict__ w_d1, const float* __restrict__ b_d1,
    const float* __restrict__ w_d2, const float* __restrict__ b_d2,
    float* __restrict__ out)
{
    __shared__ float sw1[128];
    __shared__ float sw2[16];
    __shared__ float sb1[4];
    __shared__ float sb2s;

    const int tid = threadIdx.x;
    if (tid < 128) sw1[tid] = w_d1[tid];
    else if (tid < 144) sw2[tid - 128] = w_d2[tid - 128];
    else if (tid < 148) sb1[tid - 144] = b_d1[tid - 144];
    else if (tid == 148) sb2s = b_d2[0];
    __syncthreads();

    const int w = blockIdx.x * 256 + tid;       // 0 .. 16384*196-1
    const int s = w / 196;
    const int p = w - s * 196;
    const int I = p / 14;
    const int J = p - I * 14;
    const int par = (I & 1) * 2 + (J & 1);      // (d1,k1) parity selector

    const float* hp = g_h + (size_t)s * 392 + (I >> 1) * 7 + (J >> 1);
    float hc[8];
#pragma unroll
    for (int c = 0; c < 8; c++) hc[c] = __ldg(hp + c * 49);

    // deconv1: 4 channels of y1 at (I,J)
    float y[4];
#pragma unroll
    for (int o = 0; o < 4; o++) {
        float a = sb1[o];
#pragma unroll
        for (int c = 0; c < 8; c++)
            a = fmaf(hc[c], sw1[c * 16 + o * 4 + par], a);
        y[o] = fmaxf(a, 0.f);
    }
    // deconv2 + sigmoid: 2x2 output patch at (2I, 2J)
    float v[4];
#pragma unroll
    for (int dk = 0; dk < 4; dk++) {
        float a = sb2s;
#pragma unroll
        for (int o = 0; o < 4; o++)
            a = fmaf(y[o], sw2[o * 4 + dk], a);
        v[dk] = __fdividef(1.0f, 1.0f + __expf(-a));
    }
    float* ob = out + (size_t)s * 784 + (2 * I) * 28 + 2 * J;
    *(float2*)(ob)      = make_float2(v[0], v[1]);
    *(float2*)(ob + 28) = make_float2(v[2], v[3]);
}

// ---------------------------------------------------------------------------
// Launch
// ---------------------------------------------------------------------------
extern "C" void kernel_launch(void* const* d_in, const int* in_sizes, int n_in,
                              void* d_out, int out_size)
{
    const float* x          = (const float*)d_in[0];
    const float* var_params = (const float*)d_in[1];
    const float* w_lat      = (const float*)d_in[2];
    const float* b_lat      = (const float*)d_in[3];
    const float* w_fc       = (const float*)d_in[4];
    const float* b_fc       = (const float*)d_in[5];
    const float* w_d1       = (const float*)d_in[6];
    const float* b_d1       = (const float*)d_in[7];
    const float* w_d2       = (const float*)d_in[8];
    const float* b_d2       = (const float*)d_in[9];
    float* out = (float*)d_out;

    cudaFuncSetAttribute(k2_gemm_mma, cudaFuncAttributeMaxDynamicSharedMemorySize,
                         K2_SMEM_BYTES);

    k1_quad_latent<<<BATCH / 8, 256>>>(x, var_params, w_lat, b_lat);
    k2a_convert<<<(392 * 224 / 4 + 255) / 256, 256>>>(w_fc);
    k2_gemm_mma<<<dim3(7, BATCH / 128), 256, K2_SMEM_BYTES>>>(b_fc);
    k3_deconv<<<BATCH * 196 / 256, 256>>>(w_d1, b_d1, w_d2, b_d2, out);
}

// round 7
// speedup vs baseline: 2.7739x; 1.0474x over previous
#include <cuda_runtime.h>
#include <cuda_bf16.h>
#include <math.h>
#include <cstdint>

#define BATCH 16384
__device__ __nv_bfloat16 g_latent_bf[BATCH * 224];
__device__ __nv_bfloat16 g_wfc_bf[392 * 224];
__device__ float g_h[BATCH * 392];

__device__ __forceinline__ uint32_t smem_u32(const void* p) {
    uint32_t a;
    asm("{ .reg .u64 t; cvta.to.shared.u64 t, %1; cvt.u32.u64 %0, t; }" : "=r"(a) : "l"(p));
    return a;
}
__device__ __forceinline__ void ldmatrix_x4(uint32_t& r0, uint32_t& r1, uint32_t& r2, uint32_t& r3,
                                            uint32_t addr) {
    asm volatile("ldmatrix.sync.aligned.m8n8.x4.shared.b16 {%0,%1,%2,%3}, [%4];"
                 : "=r"(r0), "=r"(r1), "=r"(r2), "=r"(r3) : "r"(addr));
}
__device__ __forceinline__ void mma_16816(float* d, const uint32_t* a, const uint32_t* b) {
    asm volatile(
        "mma.sync.aligned.m16n8k16.row.col.f32.bf16.bf16.f32 "
        "{%0,%1,%2,%3}, {%4,%5,%6,%7}, {%8,%9}, {%0,%1,%2,%3};"
        : "+f"(d[0]), "+f"(d[1]), "+f"(d[2]), "+f"(d[3])
        : "r"(a[0]), "r"(a[1]), "r"(a[2]), "r"(a[3]), "r"(b[0]), "r"(b[1]));
}

// ---------------------------------------------------------------------------
// Kernel 1: quadrant means -> 4-qubit sim -> latent (bf16) = relu(qf@w_lat^T+b)
// ---------------------------------------------------------------------------
__global__ void __launch_bounds__(256) k1_quad_latent(
    const float* __restrict__ x,
    const float* __restrict__ var_params,
    const float* __restrict__ w_lat,
    const float* __restrict__ b_lat)
{
    const int warp = threadIdx.x >> 5;
    const int lane = threadIdx.x & 31;
    const int b = blockIdx.x * 8 + warp;

    const float4* xb4 = (const float4*)(x + (size_t)b * 784);
    float q0 = 0.f, q1 = 0.f, q2 = 0.f, q3 = 0.f;
#pragma unroll
    for (int it = 0; it < 7; it++) {
        int f = lane + 32 * it;
        if (f < 196) {
            float4 v = xb4[f];
            int row = f / 7;
            int cg  = f - row * 7;
            float s4  = (v.x + v.y) + (v.z + v.w);
            float lft = (cg < 3) ? s4 : ((cg == 3) ? (v.x + v.y) : 0.f);
            float rgt = s4 - lft;
            if (row < 14) { q0 += lft; q1 += rgt; }
            else          { q2 += lft; q3 += rgt; }
        }
    }
#pragma unroll
    for (int off = 16; off; off >>= 1) {
        q0 += __shfl_xor_sync(0xFFFFFFFFu, q0, off);
        q1 += __shfl_xor_sync(0xFFFFFFFFu, q1, off);
        q2 += __shfl_xor_sync(0xFFFFFFFFu, q2, off);
        q3 += __shfl_xor_sync(0xFFFFFFFFu, q3, off);
    }
    const float inv196 = 1.0f / 196.0f;
    float ang[4] = { q0 * inv196, q1 * inv196, q2 * inv196, q3 * inv196 };

    float cc[4], ss[4];
#pragma unroll
    for (int q = 0; q < 4; q++) {
        float th = 0.5f * ang[q];
        cc[q] = __cosf(th);
        ss[q] = __sinf(th);
    }
    float re[16], im[16];
#pragma unroll
    for (int i = 0; i < 16; i++) {
        re[i] = ((i & 8) ? ss[0] : cc[0]) * ((i & 4) ? ss[1] : cc[1]) *
                ((i & 2) ? ss[2] : cc[2]) * ((i & 1) ? ss[3] : cc[3]);
        im[i] = 0.f;
    }
#pragma unroll
    for (int q = 0; q < 4; q++) {
        float ph = 0.5f * var_params[q];
        float hc = __cosf(ph), hs = __sinf(ph);
        const int mq = 8 >> q;
        const int mt = 8 >> ((q + 1) & 3);
#pragma unroll
        for (int i = 0; i < 16; i++) {
            float sg = (i & mq) ? hs : -hs;
            float nr = re[i] * hc - im[i] * sg;
            float ni = re[i] * sg + im[i] * hc;
            re[i] = nr; im[i] = ni;
        }
#pragma unroll
        for (int i = 0; i < 16; i++) {
            if ((i & mq) && !(i & mt)) {
                int j2 = i | mt;
                float tr = re[i]; re[i] = re[j2]; re[j2] = tr;
                float ti = im[i]; im[i] = im[j2]; im[j2] = ti;
            }
        }
    }
    float z0 = 0.f, z1 = 0.f, z2 = 0.f, z3 = 0.f;
#pragma unroll
    for (int i = 0; i < 16; i++) {
        float p = re[i] * re[i] + im[i] * im[i];
        z0 += (i & 8) ? -p : p;
        z1 += (i & 4) ? -p : p;
        z2 += (i & 2) ? -p : p;
        z3 += (i & 1) ? -p : p;
    }
    for (int r = lane; r < 224; r += 32) {
        float4 w = *(const float4*)(w_lat + (size_t)r * 4);
        float a = b_lat[r];
        a = fmaf(w.x, z0, a);
        a = fmaf(w.y, z1, a);
        a = fmaf(w.z, z2, a);
        a = fmaf(w.w, z3, a);
        g_latent_bf[(size_t)b * 224 + r] = __float2bfloat16(fmaxf(a, 0.f));
    }
}

// ---------------------------------------------------------------------------
// Kernel 2a: convert w_fc (392x224 fp32) -> bf16
// ---------------------------------------------------------------------------
__global__ void __launch_bounds__(256) k2a_convert(const float* __restrict__ w_fc) {
    int i = blockIdx.x * 256 + threadIdx.x;
    if (i < 392 * 224 / 4) {
        float4 v = *(const float4*)(w_fc + i * 4);
        __nv_bfloat16* d = g_wfc_bf + i * 4;
        d[0] = __float2bfloat16(v.x);
        d[1] = __float2bfloat16(v.y);
        d[2] = __float2bfloat16(v.z);
        d[3] = __float2bfloat16(v.w);
    }
}

// ---------------------------------------------------------------------------
// Kernel 2: HMMA bf16 GEMM: h = relu(latent @ w_fc^T + b_fc)
// BM=128, BN=64 (N padded to 448), 8 warps (4m x 2n), warp tile 32x32.
// ---------------------------------------------------------------------------
#define ASTR 232
#define K2_SMEM_BYTES ((128 * ASTR + 64 * ASTR) * 2)

__global__ void __launch_bounds__(256, 2) k2_gemm_mma(
    const float* __restrict__ b_fc)
{
    extern __shared__ __align__(16) __nv_bfloat16 sm[];
    __nv_bfloat16* sa = sm;               // [128][ASTR]
    __nv_bfloat16* sb = sm + 128 * ASTR;  // [64][ASTR]

    const int tid = threadIdx.x;
    const int wid = tid >> 5;
    const int lane = tid & 31;
    const int n0 = blockIdx.x * 64;
    const int m0 = blockIdx.y * 128;
    const int mw = (wid & 3) * 32;
    const int nw = (wid >> 2) * 32;

    for (int t = tid; t < 128 * 28; t += 256) {
        int r = t / 28, c = t - (t / 28) * 28;
        uint4 v = *(const uint4*)(g_latent_bf + (size_t)(m0 + r) * 224 + c * 8);
        *(uint4*)(sa + r * ASTR + c * 8) = v;
    }
    for (int t = tid; t < 64 * 28; t += 256) {
        int r = t / 28, c = t - (t / 28) * 28;
        int gn = n0 + r;
        uint4 v = make_uint4(0u, 0u, 0u, 0u);
        if (gn < 392) v = *(const uint4*)(g_wfc_bf + (size_t)gn * 224 + c * 8);
        *(uint4*)(sb + r * ASTR + c * 8) = v;
    }
    __syncthreads();

    float d[2][4][4];
#pragma unroll
    for (int mt = 0; mt < 2; mt++)
#pragma unroll
        for (int nt = 0; nt < 4; nt++)
#pragma unroll
            for (int e = 0; e < 4; e++) d[mt][nt][e] = 0.f;

    const uint32_t sa_base = smem_u32(sa);
    const uint32_t sb_base = smem_u32(sb);
    const int a_row = mw + (lane & 15);
    const int a_coff = (lane >> 4) * 8;
    const int b_row = nw + (lane & 7) + ((lane >> 4) & 1) * 8;
    const int b_coff = ((lane >> 3) & 1) * 8;

#pragma unroll
    for (int ks = 0; ks < 14; ks++) {
        const int k0 = ks * 16;
        uint32_t a0[4], a1[4];
        ldmatrix_x4(a0[0], a0[1], a0[2], a0[3],
                    sa_base + (uint32_t)((a_row) * ASTR + k0 + a_coff) * 2);
        ldmatrix_x4(a1[0], a1[1], a1[2], a1[3],
                    sa_base + (uint32_t)((a_row + 16) * ASTR + k0 + a_coff) * 2);
        uint32_t b01[4], b23[4];
        ldmatrix_x4(b01[0], b01[1], b01[2], b01[3],
                    sb_base + (uint32_t)((b_row) * ASTR + k0 + b_coff) * 2);
        ldmatrix_x4(b23[0], b23[1], b23[2], b23[3],
                    sb_base + (uint32_t)((b_row + 16) * ASTR + k0 + b_coff) * 2);
        mma_16816(d[0][0], a0, b01 + 0);
        mma_16816(d[0][1], a0, b01 + 2);
        mma_16816(d[0][2], a0, b23 + 0);
        mma_16816(d[0][3], a0, b23 + 2);
        mma_16816(d[1][0], a1, b01 + 0);
        mma_16816(d[1][1], a1, b01 + 2);
        mma_16816(d[1][2], a1, b23 + 0);
        mma_16816(d[1][3], a1, b23 + 2);
    }

    const int qrow = lane >> 2;
    const int qcol = (lane & 3) * 2;
#pragma unroll
    for (int nt = 0; nt < 4; nt++) {
        int gn = n0 + nw + nt * 8 + qcol;
        if (gn < 392) {
            float2 bv = *(const float2*)(b_fc + gn);
#pragma unroll
            for (int mt = 0; mt < 2; mt++) {
                int m = m0 + mw + mt * 16 + qrow;
                float2 o0, o1;
                o0.x = fmaxf(d[mt][nt][0] + bv.x, 0.f);
                o0.y = fmaxf(d[mt][nt][1] + bv.y, 0.f);
                o1.x = fmaxf(d[mt][nt][2] + bv.x, 0.f);
                o1.y = fmaxf(d[mt][nt][3] + bv.y, 0.f);
                *(float2*)(g_h + (size_t)m * 392 + gn) = o0;
                *(float2*)(g_h + (size_t)(m + 8) * 392 + gn) = o1;
            }
        }
    }
}

// ---------------------------------------------------------------------------
// Kernel 3: fused deconv1+relu+deconv2+sigmoid.
// Block = 256 threads handles 4 samples. h (4x392 contiguous floats) staged
// to smem with coalesced float4 loads; per-item channel reads hit smem
// (broadcast-heavy, low conflict). One item = (s,I,J) -> 2x2 output patch.
// ---------------------------------------------------------------------------
__global__ void __launch_bounds__(256) k3_deconv(
    const float* __restrict__ w_d1, const float* __restrict__ b_d1,
    const float* __restrict__ w_d2, const float* __restrict__ b_d2,
    float* __restrict__ out)
{
    __shared__ float shh[4 * 392];
    __shared__ float sw1[128];
    __shared__ float sw2[16];
    __shared__ float sb1[4];
    __shared__ float sb2s;

    const int tid = threadIdx.x;
    const int b0 = blockIdx.x * 4;

    if (tid < 128) sw1[tid] = w_d1[tid];
    else if (tid < 144) sw2[tid - 128] = w_d2[tid - 128];
    else if (tid < 148) sb1[tid - 144] = b_d1[tid - 144];
    else if (tid == 148) sb2s = b_d2[0];

    // stage 4 samples of h: 1568 contiguous floats = 392 float4, coalesced
    {
        const float4* src = (const float4*)(g_h + (size_t)b0 * 392);
        float4* dst = (float4*)shh;
        dst[tid] = src[tid];
        if (tid < 136) dst[256 + tid] = src[256 + tid];
    }
    __syncthreads();

#pragma unroll
    for (int idx = tid; idx < 784; idx += 256) {
        const int s  = idx / 196;
        const int p  = idx - s * 196;
        const int I  = p / 14;
        const int J  = p - I * 14;
        const int par = (I & 1) * 2 + (J & 1);

        const float* hp = shh + s * 392 + (I >> 1) * 7 + (J >> 1);
        float hc[8];
#pragma unroll
        for (int c = 0; c < 8; c++) hc[c] = hp[c * 49];

        float y[4];
#pragma unroll
        for (int o = 0; o < 4; o++) {
            float a = sb1[o];
#pragma unroll
            for (int c = 0; c < 8; c++)
                a = fmaf(hc[c], sw1[c * 16 + o * 4 + par], a);
            y[o] = fmaxf(a, 0.f);
        }
        float v[4];
#pragma unroll
        for (int dk = 0; dk < 4; dk++) {
            float a = sb2s;
#pragma unroll
            for (int o = 0; o < 4; o++)
                a = fmaf(y[o], sw2[o * 4 + dk], a);
            v[dk] = __fdividef(1.0f, 1.0f + __expf(-a));
        }
        float* ob = out + (size_t)(b0 + s) * 784 + (2 * I) * 28 + 2 * J;
        *(float2*)(ob)      = make_float2(v[0], v[1]);
        *(float2*)(ob + 28) = make_float2(v[2], v[3]);
    }
}

// ---------------------------------------------------------------------------
// Launch
// ---------------------------------------------------------------------------
extern "C" void kernel_launch(void* const* d_in, const int* in_sizes, int n_in,
                              void* d_out, int out_size)
{
    const float* x          = (const float*)d_in[0];
    const float* var_params = (const float*)d_in[1];
    const float* w_lat      = (const float*)d_in[2];
    const float* b_lat      = (const float*)d_in[3];
    const float* w_fc       = (const float*)d_in[4];
    const float* b_fc       = (const float*)d_in[5];
    const float* w_d1       = (const float*)d_in[6];
    const float* b_d1       = (const float*)d_in[7];
    const float* w_d2       = (const float*)d_in[8];
    const float* b_d2       = (const float*)d_in[9];
    float* out = (float*)d_out;

    cudaFuncSetAttribute(k2_gemm_mma, cudaFuncAttributeMaxDynamicSharedMemorySize,
                         K2_SMEM_BYTES);

    k1_quad_latent<<<BATCH / 8, 256>>>(x, var_params, w_lat, b_lat);
    k2a_convert<<<(392 * 224 / 4 + 255) / 256, 256>>>(w_fc);
    k2_gemm_mma<<<dim3(7, BATCH / 128), 256, K2_SMEM_BYTES>>>(b_fc);
    k3_deconv<<<BATCH / 4, 256>>>(w_d1, b_d1, w_d2, b_d2, out);
}